// round 16
// baseline (speedup 1.0000x reference)
#include <cuda_runtime.h>
#include <cuda_fp16.h>
#include <cstdint>

#define NN 100000
#define EE 1600000
#define GEMM_BLOCKS ((NN + 63) / 64)
#define CNT_BLOCKS 160
#define SCAN_BLOCKS ((NN + 1023) / 1024)   // 98

// Scratch (device globals: allocation-free; g_cnt restored to 0 by agg_csr,
// g_total by k1, g_stats by scan_alloc -> no memset nodes needed)
__device__ __half g_Ph[NN * 64];   // fp16 P = feat @ (W1-W2)^T
__device__ __half g_Qh[NN * 64];   // fp16 Q = feat @ W2^T
__device__ int    g_cnt[NN];       // in-degree
__device__ int    g_off[NN];       // CSR row offsets (any disjoint layout)
__device__ int    g_cursor[NN];    // fill cursors
__device__ int    g_total;         // scan base allocator
__device__ int    g_csr[EE];       // src indices grouped by dst
__device__ double g_stats[128];    // [0:64) sum, [64:128) sumsq

#define FFMA2(acc, x, w) \
    asm("fma.rn.f32x2 %0, %1, %2, %3;" : "=l"(acc) : "l"(x), "l"(w), "l"(acc))

// ---------------------------------------------------------------------------
// Kernel 1: heterogeneous launch (R14 proven config): GEMM blocks
// (256 thr, j=4, f32x2 FFMA) + degree-count blocks.
// ---------------------------------------------------------------------------
__global__ __launch_bounds__(256) void gemm_pq_cnt(const float* __restrict__ feat,
                                                   const float* __restrict__ W,
                                                   const int* __restrict__ ei) {
    if (blockIdx.x >= GEMM_BLOCKS) {
        if (blockIdx.x == GEMM_BLOCKS && threadIdx.x == 0) g_total = 0;
        int t0 = (blockIdx.x - GEMM_BLOCKS) * 256 + threadIdx.x;
        const int stride = CNT_BLOCKS * 256;
        const int4* d4 = reinterpret_cast<const int4*>(ei + EE);
        for (int e = t0; e < EE / 4; e += stride) {
            int4 d = __ldg(&d4[e]);
            atomicAdd(&g_cnt[d.x], 1);
            atomicAdd(&g_cnt[d.y], 1);
            atomicAdd(&g_cnt[d.z], 1);
            atomicAdd(&g_cnt[d.w], 1);
        }
        return;
    }

    __shared__ float Wsh[64][128];  // [k][c']: c'<64 -> W1-W2, c'>=64 -> W2
    __shared__ float Xsh[64][64];   // [node][k]

    for (int i = threadIdx.x; i < 64 * 64; i += 256) {
        int c = i >> 6, k = i & 63;
        float w1 = W[c * 128 + k];
        float w2 = W[c * 128 + 64 + k];
        Wsh[k][c]      = w1 - w2;
        Wsh[k][64 + c] = w2;
    }
    int node0 = blockIdx.x * 64;
    for (int i = threadIdx.x; i < 64 * 16; i += 256) {
        int n = i >> 4, v = i & 15;
        int gn = node0 + n;
        if (gn >= NN) gn = NN - 1;
        float4 x = reinterpret_cast<const float4*>(feat)[gn * 16 + v];
        *reinterpret_cast<float4*>(&Xsh[n][v * 4]) = x;
    }
    __syncthreads();

    const int tx = threadIdx.x & 15;   // channel group: 8 channels (4 f32x2)
    const int ty = threadIdx.x >> 4;   // node group: 4 nodes
    unsigned long long acc2[4][4] = {};

#pragma unroll
    for (int k0 = 0; k0 < 64; k0 += 4) {
        float4 xr[4];
#pragma unroll
        for (int j = 0; j < 4; j++)
            xr[j] = *reinterpret_cast<const float4*>(&Xsh[ty * 4 + j][k0]);
#pragma unroll
        for (int kk = 0; kk < 4; kk++) {
            ulonglong2 wlo = *reinterpret_cast<const ulonglong2*>(&Wsh[k0 + kk][tx * 8]);
            ulonglong2 whi = *reinterpret_cast<const ulonglong2*>(&Wsh[k0 + kk][tx * 8 + 4]);
#pragma unroll
            for (int j = 0; j < 4; j++) {
                float xv = reinterpret_cast<const float*>(&xr[j])[kk];
                unsigned long long xx;
                asm("mov.b64 %0, {%1, %1};" : "=l"(xx) : "f"(xv));
                FFMA2(acc2[j][0], xx, wlo.x);
                FFMA2(acc2[j][1], xx, wlo.y);
                FFMA2(acc2[j][2], xx, whi.x);
                FFMA2(acc2[j][3], xx, whi.y);
            }
        }
    }

    const int cbase = tx * 8;
#pragma unroll
    for (int j = 0; j < 4; j++) {
        int gn = node0 + ty * 4 + j;
        if (gn >= NN) continue;
        uint4 hv;
        unsigned* hw = reinterpret_cast<unsigned*>(&hv);
#pragma unroll
        for (int p = 0; p < 4; p++) {
            float lo, hi;
            asm("mov.b64 {%0, %1}, %2;" : "=f"(lo), "=f"(hi) : "l"(acc2[j][p]));
            *reinterpret_cast<__half2*>(&hw[p]) = __floats2half2_rn(lo, hi);
        }
        __half* base = (cbase < 64) ? &g_Ph[gn * 64 + cbase]
                                    : &g_Qh[gn * 64 + (cbase - 64)];
        *reinterpret_cast<uint4*>(base) = hv;
    }
}

// ---------------------------------------------------------------------------
// Kernel 2: single-launch scan (atomic ticket bases). Also zeroes g_stats.
// ---------------------------------------------------------------------------
__global__ __launch_bounds__(1024) void scan_alloc() {
    if (blockIdx.x == 0 && threadIdx.x < 128) g_stats[threadIdx.x] = 0.0;
    __shared__ int wsum[32];
    __shared__ int gbase;
    int i = blockIdx.x * 1024 + threadIdx.x;
    int v = (i < NN) ? g_cnt[i] : 0;
    int lane = threadIdx.x & 31, wid = threadIdx.x >> 5;
    int x = v;
#pragma unroll
    for (int d = 1; d < 32; d <<= 1) {
        int y = __shfl_up_sync(0xffffffffu, x, d);
        if (lane >= d) x += y;
    }
    if (lane == 31) wsum[wid] = x;
    __syncthreads();
    if (wid == 0) {
        int w = wsum[lane];
#pragma unroll
        for (int d = 1; d < 32; d <<= 1) {
            int y = __shfl_up_sync(0xffffffffu, w, d);
            if (lane >= d) w += y;
        }
        wsum[lane] = w;
        if (lane == 31) gbase = atomicAdd(&g_total, w);
    }
    __syncthreads();
    int base = gbase + ((wid > 0) ? wsum[wid - 1] : 0);
    if (i < NN) {
        int o = base + x - v;
        g_off[i] = o;
        g_cursor[i] = o;
    }
}

// ---------------------------------------------------------------------------
// Kernel 3: CSR fill (counting-sort edges by dst), 4 edges/thread.
// ---------------------------------------------------------------------------
__global__ __launch_bounds__(256) void csr_fill(const int* __restrict__ ei) {
    int t = blockIdx.x * 256 + threadIdx.x;
    if (t >= EE / 4) return;
    const int4* s4 = reinterpret_cast<const int4*>(ei);
    const int4* d4 = reinterpret_cast<const int4*>(ei + EE);
    int4 s = __ldg(&s4[t]);
    int4 d = __ldg(&d4[t]);
    g_csr[atomicAdd(&g_cursor[d.x], 1)] = s.x;
    g_csr[atomicAdd(&g_cursor[d.y], 1)] = s.y;
    g_csr[atomicAdd(&g_cursor[d.z], 1)] = s.z;
    g_csr[atomicAdd(&g_cursor[d.w], 1)] = s.w;
}

// ---------------------------------------------------------------------------
// Kernel 4: BN stats via CSR — proven loop (54us, 32 regs, occ 88%).
// One warp per node (grid-stride); 2 edges per round; fp32 t/t^2.
// ---------------------------------------------------------------------------
__global__ __launch_bounds__(256) void edge_stats_csr() {
    const int lane = threadIdx.x & 31;
    const int li = lane & 15;
    const int h = lane >> 4;
    const int warp0 = (blockIdx.x * 256 + threadIdx.x) >> 5;
    const int nwarp = (gridDim.x * 256) >> 5;
    const uint2* P2 = reinterpret_cast<const uint2*>(g_Ph);
    const uint2* Q2 = reinterpret_cast<const uint2*>(g_Qh);

    float s[4] = {0.f, 0.f, 0.f, 0.f};
    float q[4] = {0.f, 0.f, 0.f, 0.f};

    for (int n = warp0; n < NN; n += nwarp) {
        int deg = g_cnt[n];
        if (deg == 0) continue;
        int start = g_off[n];
        uint2 pw = P2[n * 16 + li];
        float2 pa = __half22float2(*reinterpret_cast<const __half2*>(&pw.x));
        float2 pb = __half22float2(*reinterpret_cast<const __half2*>(&pw.y));
        for (int j = 0; j < deg; j += 32) {
            int m = min(32, deg - j);
            int my = (j + lane < deg) ? g_csr[start + j + lane] : 0;
            int m2 = (m + 1) >> 1;
            for (int i = 0; i < m2; i++) {
                int idx = 2 * i + h;
                int src = __shfl_sync(0xffffffffu, my, idx);
                if (idx < m) {
                    uint2 qw = Q2[src * 16 + li];
                    float2 qa = __half22float2(*reinterpret_cast<const __half2*>(&qw.x));
                    float2 qb = __half22float2(*reinterpret_cast<const __half2*>(&qw.y));
                    float t0 = pa.x + qa.x, t1 = pa.y + qa.y;
                    float t2 = pb.x + qb.x, t3 = pb.y + qb.y;
                    s[0] += t0; s[1] += t1; s[2] += t2; s[3] += t3;
                    q[0] = fmaf(t0, t0, q[0]);
                    q[1] = fmaf(t1, t1, q[1]);
                    q[2] = fmaf(t2, t2, q[2]);
                    q[3] = fmaf(t3, t3, q[3]);
                }
            }
        }
    }

#pragma unroll
    for (int k = 0; k < 4; k++) {
        s[k] += __shfl_down_sync(0xffffffffu, s[k], 16);
        q[k] += __shfl_down_sync(0xffffffffu, q[k], 16);
    }

    __shared__ float ssum[64], ssq[64];
    if (threadIdx.x < 64) { ssum[threadIdx.x] = 0.f; ssq[threadIdx.x] = 0.f; }
    __syncthreads();
    if (h == 0) {
#pragma unroll
        for (int k = 0; k < 4; k++) {
            atomicAdd(&ssum[4 * li + k], s[k]);
            atomicAdd(&ssq[4 * li + k], q[k]);
        }
    }
    __syncthreads();
    if (threadIdx.x < 64) {
        atomicAdd(&g_stats[threadIdx.x], (double)ssum[threadIdx.x]);
        atomicAdd(&g_stats[64 + threadIdx.x], (double)ssq[threadIdx.x]);
    }
}

// ---------------------------------------------------------------------------
// Kernel 5: aggregation — stats-shaped persistent loop (R14, proven) +
// restores g_cnt[n]=0 (last reader) so no memset node is needed.
// ---------------------------------------------------------------------------
__global__ __launch_bounds__(256) void agg_csr(float* __restrict__ out,
                                               const float* __restrict__ gamma,
                                               const float* __restrict__ beta) {
    __shared__ float  fscale[64], fshift[64];
    __shared__ __half2 sscale2[32], sshift2[32];
    if (threadIdx.x < 64) {
        int c = threadIdx.x;
        double inv_e = 1.0 / (double)EE;
        double mean = g_stats[c] * inv_e;
        double var = g_stats[64 + c] * inv_e - mean * mean;
        float scale = __ldg(&gamma[c]) * rsqrtf((float)var + 1e-5f);
        fscale[c] = scale;
        fshift[c] = fmaf(-(float)mean, scale, __ldg(&beta[c]));
    }
    __syncthreads();
    if (threadIdx.x < 32) {
        int c = threadIdx.x;
        sscale2[c] = __floats2half2_rn(fscale[2 * c], fscale[2 * c + 1]);
        sshift2[c] = __floats2half2_rn(fshift[2 * c], fshift[2 * c + 1]);
    }
    __syncthreads();

    const int lane = threadIdx.x & 31;
    const int li = lane & 15;
    const int h = lane >> 4;
    const int warp0 = (blockIdx.x * 256 + threadIdx.x) >> 5;
    const int nwarp = (gridDim.x * 256) >> 5;
    const uint2* P2 = reinterpret_cast<const uint2*>(g_Ph);
    const uint2* Q2 = reinterpret_cast<const uint2*>(g_Qh);
    const __half2 sc2a = sscale2[2 * li],     sh2a = sshift2[2 * li];
    const __half2 sc2b = sscale2[2 * li + 1], sh2b = sshift2[2 * li + 1];
    const __half2 slope = __floats2half2_rn(0.3f, 0.3f);

    for (int n = warp0; n < NN; n += nwarp) {
        int deg = g_cnt[n];
        if (lane == 0) g_cnt[n] = 0;   // restore zero state for next replay
        float a0 = 0.f, a1 = 0.f, a2 = 0.f, a3 = 0.f;
        if (deg > 0) {
            int start = g_off[n];
            uint2 pw = P2[n * 16 + li];
            __half2 pa = *reinterpret_cast<const __half2*>(&pw.x);
            __half2 pb = *reinterpret_cast<const __half2*>(&pw.y);
            for (int j = 0; j < deg; j += 32) {
                int m = min(32, deg - j);
                int my = (j + lane < deg) ? g_csr[start + j + lane] : 0;
                int m2 = (m + 1) >> 1;
                for (int i = 0; i < m2; i++) {
                    int idx = 2 * i + h;
                    int src = __shfl_sync(0xffffffffu, my, idx);
                    if (idx < m) {
                        uint2 qw = Q2[src * 16 + li];
                        __half2 qa = *reinterpret_cast<const __half2*>(&qw.x);
                        __half2 qb = *reinterpret_cast<const __half2*>(&qw.y);
                        __half2 ta = __hadd2(pa, qa);
                        __half2 tb = __hadd2(pb, qb);
                        __half2 va = __hfma2(ta, sc2a, sh2a);
                        __half2 vb = __hfma2(tb, sc2b, sh2b);
                        __half2 ya = __hmax2(va, __hmul2(va, slope));
                        __half2 yb = __hmax2(vb, __hmul2(vb, slope));
                        float2 fa = __half22float2(ya);
                        float2 fb = __half22float2(yb);
                        a0 += fa.x; a1 += fa.y; a2 += fb.x; a3 += fb.y;
                    }
                }
            }
        }
        a0 += __shfl_down_sync(0xffffffffu, a0, 16);
        a1 += __shfl_down_sync(0xffffffffu, a1, 16);
        a2 += __shfl_down_sync(0xffffffffu, a2, 16);
        a3 += __shfl_down_sync(0xffffffffu, a3, 16);
        if (h == 0) {
            float inv = (deg > 0) ? (1.0f / (float)deg) : 0.f;
            float4 r = make_float4(a0 * inv, a1 * inv, a2 * inv, a3 * inv);
            *reinterpret_cast<float4*>(&out[(size_t)n * 64 + 4 * li]) = r;
        }
    }
}

// ---------------------------------------------------------------------------
extern "C" void kernel_launch(void* const* d_in, const int* in_sizes, int n_in,
                              void* d_out, int out_size) {
    const float* feat  = (const float*)d_in[0];
    const int*   ei    = (const int*)d_in[1];
    const float* W     = (const float*)d_in[2];
    // d_in[3] = b: cancels out of BN, unused
    const float* gamma = (const float*)d_in[4];
    const float* beta  = (const float*)d_in[5];
    float* out = (float*)d_out;

    gemm_pq_cnt<<<GEMM_BLOCKS + CNT_BLOCKS, 256>>>(feat, W, ei);
    scan_alloc<<<SCAN_BLOCKS, 1024>>>();
    csr_fill<<<(EE / 4 + 255) / 256, 256>>>(ei);
    edge_stats_csr<<<1184, 256>>>();
    agg_csr<<<1184, 256>>>(out, gamma, beta);
}

// round 17
// speedup vs baseline: 1.4087x; 1.4087x over previous
#include <cuda_runtime.h>
#include <cuda_fp16.h>
#include <cstdint>

#define NN 100000
#define EE 1600000
#define GEMM_BLOCKS ((NN + 63) / 64)
#define CNT_BLOCKS 160
#define SCAN_BLOCKS ((NN + 1023) / 1024)   // 98

// Scratch (device globals: allocation-free)
__device__ __half g_Ph[NN * 64];   // fp16 P = feat @ (W1-W2)^T
__device__ __half g_Qh[NN * 64];   // fp16 Q = feat @ W2^T
__device__ int    g_cnt[NN];       // in-degree (zeroed by memset node)
__device__ int    g_off[NN];       // CSR row offsets (any disjoint layout)
__device__ int    g_cursor[NN];    // fill cursors
__device__ int    g_total;         // scan base allocator
__device__ int    g_csr[EE];       // src indices grouped by dst
__device__ double g_stats[128];    // [0:64) sum, [64:128) sumsq

#define FFMA2(acc, x, w) \
    asm("fma.rn.f32x2 %0, %1, %2, %3;" : "=l"(acc) : "l"(x), "l"(w), "l"(acc))

// ---------------------------------------------------------------------------
// Kernel 1: heterogeneous launch. Count blocks FIRST (wave-1, hidden under
// the GEMM waves instead of extending the tail); GEMM blocks after
// (256 thr, j=4, f32x2 FFMA — proven R14 config).
// ---------------------------------------------------------------------------
__global__ __launch_bounds__(256) void gemm_pq_cnt(const float* __restrict__ feat,
                                                   const float* __restrict__ W,
                                                   const int* __restrict__ ei) {
    if (blockIdx.x < CNT_BLOCKS) {
        if (blockIdx.x == 0 && threadIdx.x == 0) g_total = 0;
        int t0 = blockIdx.x * 256 + threadIdx.x;
        const int stride = CNT_BLOCKS * 256;
        const int4* d4 = reinterpret_cast<const int4*>(ei + EE);
        for (int e = t0; e < EE / 4; e += stride) {
            int4 d = __ldg(&d4[e]);
            atomicAdd(&g_cnt[d.x], 1);
            atomicAdd(&g_cnt[d.y], 1);
            atomicAdd(&g_cnt[d.z], 1);
            atomicAdd(&g_cnt[d.w], 1);
        }
        return;
    }

    __shared__ float Wsh[64][128];  // [k][c']: c'<64 -> W1-W2, c'>=64 -> W2
    __shared__ float Xsh[64][64];   // [node][k]

    for (int i = threadIdx.x; i < 64 * 64; i += 256) {
        int c = i >> 6, k = i & 63;
        float w1 = W[c * 128 + k];
        float w2 = W[c * 128 + 64 + k];
        Wsh[k][c]      = w1 - w2;
        Wsh[k][64 + c] = w2;
    }
    int node0 = (blockIdx.x - CNT_BLOCKS) * 64;
    for (int i = threadIdx.x; i < 64 * 16; i += 256) {
        int n = i >> 4, v = i & 15;
        int gn = node0 + n;
        if (gn >= NN) gn = NN - 1;
        float4 x = reinterpret_cast<const float4*>(feat)[gn * 16 + v];
        *reinterpret_cast<float4*>(&Xsh[n][v * 4]) = x;
    }
    __syncthreads();

    const int tx = threadIdx.x & 15;   // channel group: 8 channels (4 f32x2)
    const int ty = threadIdx.x >> 4;   // node group: 4 nodes
    unsigned long long acc2[4][4] = {};

#pragma unroll
    for (int k0 = 0; k0 < 64; k0 += 4) {
        float4 xr[4];
#pragma unroll
        for (int j = 0; j < 4; j++)
            xr[j] = *reinterpret_cast<const float4*>(&Xsh[ty * 4 + j][k0]);
#pragma unroll
        for (int kk = 0; kk < 4; kk++) {
            ulonglong2 wlo = *reinterpret_cast<const ulonglong2*>(&Wsh[k0 + kk][tx * 8]);
            ulonglong2 whi = *reinterpret_cast<const ulonglong2*>(&Wsh[k0 + kk][tx * 8 + 4]);
#pragma unroll
            for (int j = 0; j < 4; j++) {
                float xv = reinterpret_cast<const float*>(&xr[j])[kk];
                unsigned long long xx;
                asm("mov.b64 %0, {%1, %1};" : "=l"(xx) : "f"(xv));
                FFMA2(acc2[j][0], xx, wlo.x);
                FFMA2(acc2[j][1], xx, wlo.y);
                FFMA2(acc2[j][2], xx, whi.x);
                FFMA2(acc2[j][3], xx, whi.y);
            }
        }
    }

    const int cbase = tx * 8;
#pragma unroll
    for (int j = 0; j < 4; j++) {
        int gn = node0 + ty * 4 + j;
        if (gn >= NN) continue;
        uint4 hv;
        unsigned* hw = reinterpret_cast<unsigned*>(&hv);
#pragma unroll
        for (int p = 0; p < 4; p++) {
            float lo, hi;
            asm("mov.b64 {%0, %1}, %2;" : "=f"(lo), "=f"(hi) : "l"(acc2[j][p]));
            *reinterpret_cast<__half2*>(&hw[p]) = __floats2half2_rn(lo, hi);
        }
        __half* base = (cbase < 64) ? &g_Ph[gn * 64 + cbase]
                                    : &g_Qh[gn * 64 + (cbase - 64)];
        *reinterpret_cast<uint4*>(base) = hv;
    }
}

// ---------------------------------------------------------------------------
// Kernel 2: single-launch scan (atomic ticket bases). Also zeroes g_stats.
// ---------------------------------------------------------------------------
__global__ __launch_bounds__(1024) void scan_alloc() {
    if (blockIdx.x == 0 && threadIdx.x < 128) g_stats[threadIdx.x] = 0.0;
    __shared__ int wsum[32];
    __shared__ int gbase;
    int i = blockIdx.x * 1024 + threadIdx.x;
    int v = (i < NN) ? g_cnt[i] : 0;
    int lane = threadIdx.x & 31, wid = threadIdx.x >> 5;
    int x = v;
#pragma unroll
    for (int d = 1; d < 32; d <<= 1) {
        int y = __shfl_up_sync(0xffffffffu, x, d);
        if (lane >= d) x += y;
    }
    if (lane == 31) wsum[wid] = x;
    __syncthreads();
    if (wid == 0) {
        int w = wsum[lane];
#pragma unroll
        for (int d = 1; d < 32; d <<= 1) {
            int y = __shfl_up_sync(0xffffffffu, w, d);
            if (lane >= d) w += y;
        }
        wsum[lane] = w;
        if (lane == 31) gbase = atomicAdd(&g_total, w);
    }
    __syncthreads();
    int base = gbase + ((wid > 0) ? wsum[wid - 1] : 0);
    if (i < NN) {
        int o = base + x - v;
        g_off[i] = o;
        g_cursor[i] = o;
    }
}

// ---------------------------------------------------------------------------
// Kernel 3: CSR fill (counting-sort edges by dst), 4 edges/thread.
// ---------------------------------------------------------------------------
__global__ __launch_bounds__(256) void csr_fill(const int* __restrict__ ei) {
    int t = blockIdx.x * 256 + threadIdx.x;
    if (t >= EE / 4) return;
    const int4* s4 = reinterpret_cast<const int4*>(ei);
    const int4* d4 = reinterpret_cast<const int4*>(ei + EE);
    int4 s = __ldg(&s4[t]);
    int4 d = __ldg(&d4[t]);
    g_csr[atomicAdd(&g_cursor[d.x], 1)] = s.x;
    g_csr[atomicAdd(&g_cursor[d.y], 1)] = s.y;
    g_csr[atomicAdd(&g_cursor[d.z], 1)] = s.z;
    g_csr[atomicAdd(&g_cursor[d.w], 1)] = s.w;
}

// ---------------------------------------------------------------------------
// Kernel 4: BN stats via CSR — proven loop (54us, 32 regs, occ 88%).
// One warp per node (grid-stride); 2 edges per round; fp32 t/t^2.
// ---------------------------------------------------------------------------
__global__ __launch_bounds__(256) void edge_stats_csr() {
    const int lane = threadIdx.x & 31;
    const int li = lane & 15;
    const int h = lane >> 4;
    const int warp0 = (blockIdx.x * 256 + threadIdx.x) >> 5;
    const int nwarp = (gridDim.x * 256) >> 5;
    const uint2* P2 = reinterpret_cast<const uint2*>(g_Ph);
    const uint2* Q2 = reinterpret_cast<const uint2*>(g_Qh);

    float s[4] = {0.f, 0.f, 0.f, 0.f};
    float q[4] = {0.f, 0.f, 0.f, 0.f};

    for (int n = warp0; n < NN; n += nwarp) {
        int deg = g_cnt[n];
        if (deg == 0) continue;
        int start = g_off[n];
        uint2 pw = P2[n * 16 + li];
        float2 pa = __half22float2(*reinterpret_cast<const __half2*>(&pw.x));
        float2 pb = __half22float2(*reinterpret_cast<const __half2*>(&pw.y));
        for (int j = 0; j < deg; j += 32) {
            int m = min(32, deg - j);
            int my = (j + lane < deg) ? g_csr[start + j + lane] : 0;
            int m2 = (m + 1) >> 1;
            for (int i = 0; i < m2; i++) {
                int idx = 2 * i + h;
                int src = __shfl_sync(0xffffffffu, my, idx);
                if (idx < m) {
                    uint2 qw = Q2[src * 16 + li];
                    float2 qa = __half22float2(*reinterpret_cast<const __half2*>(&qw.x));
                    float2 qb = __half22float2(*reinterpret_cast<const __half2*>(&qw.y));
                    float t0 = pa.x + qa.x, t1 = pa.y + qa.y;
                    float t2 = pb.x + qb.x, t3 = pb.y + qb.y;
                    s[0] += t0; s[1] += t1; s[2] += t2; s[3] += t3;
                    q[0] = fmaf(t0, t0, q[0]);
                    q[1] = fmaf(t1, t1, q[1]);
                    q[2] = fmaf(t2, t2, q[2]);
                    q[3] = fmaf(t3, t3, q[3]);
                }
            }
        }
    }

#pragma unroll
    for (int k = 0; k < 4; k++) {
        s[k] += __shfl_down_sync(0xffffffffu, s[k], 16);
        q[k] += __shfl_down_sync(0xffffffffu, q[k], 16);
    }

    __shared__ float ssum[64], ssq[64];
    if (threadIdx.x < 64) { ssum[threadIdx.x] = 0.f; ssq[threadIdx.x] = 0.f; }
    __syncthreads();
    if (h == 0) {
#pragma unroll
        for (int k = 0; k < 4; k++) {
            atomicAdd(&ssum[4 * li + k], s[k]);
            atomicAdd(&ssq[4 * li + k], q[k]);
        }
    }
    __syncthreads();
    if (threadIdx.x < 64) {
        atomicAdd(&g_stats[threadIdx.x], (double)ssum[threadIdx.x]);
        atomicAdd(&g_stats[64 + threadIdx.x], (double)ssq[threadIdx.x]);
    }
}

// ---------------------------------------------------------------------------
// Kernel 5: aggregation — stats-shaped persistent loop (R14 exact: no g_cnt
// stores here; mixing stores into the hot load stream measured -90us).
// ---------------------------------------------------------------------------
__global__ __launch_bounds__(256) void agg_csr(float* __restrict__ out,
                                               const float* __restrict__ gamma,
                                               const float* __restrict__ beta) {
    __shared__ float  fscale[64], fshift[64];
    __shared__ __half2 sscale2[32], sshift2[32];
    if (threadIdx.x < 64) {
        int c = threadIdx.x;
        double inv_e = 1.0 / (double)EE;
        double mean = g_stats[c] * inv_e;
        double var = g_stats[64 + c] * inv_e - mean * mean;
        float scale = __ldg(&gamma[c]) * rsqrtf((float)var + 1e-5f);
        fscale[c] = scale;
        fshift[c] = fmaf(-(float)mean, scale, __ldg(&beta[c]));
    }
    __syncthreads();
    if (threadIdx.x < 32) {
        int c = threadIdx.x;
        sscale2[c] = __floats2half2_rn(fscale[2 * c], fscale[2 * c + 1]);
        sshift2[c] = __floats2half2_rn(fshift[2 * c], fshift[2 * c + 1]);
    }
    __syncthreads();

    const int lane = threadIdx.x & 31;
    const int li = lane & 15;
    const int h = lane >> 4;
    const int warp0 = (blockIdx.x * 256 + threadIdx.x) >> 5;
    const int nwarp = (gridDim.x * 256) >> 5;
    const uint2* P2 = reinterpret_cast<const uint2*>(g_Ph);
    const uint2* Q2 = reinterpret_cast<const uint2*>(g_Qh);
    const __half2 sc2a = sscale2[2 * li],     sh2a = sshift2[2 * li];
    const __half2 sc2b = sscale2[2 * li + 1], sh2b = sshift2[2 * li + 1];
    const __half2 slope = __floats2half2_rn(0.3f, 0.3f);

    for (int n = warp0; n < NN; n += nwarp) {
        int deg = g_cnt[n];
        float a0 = 0.f, a1 = 0.f, a2 = 0.f, a3 = 0.f;
        if (deg > 0) {
            int start = g_off[n];
            uint2 pw = P2[n * 16 + li];
            __half2 pa = *reinterpret_cast<const __half2*>(&pw.x);
            __half2 pb = *reinterpret_cast<const __half2*>(&pw.y);
            for (int j = 0; j < deg; j += 32) {
                int m = min(32, deg - j);
                int my = (j + lane < deg) ? g_csr[start + j + lane] : 0;
                int m2 = (m + 1) >> 1;
                for (int i = 0; i < m2; i++) {
                    int idx = 2 * i + h;
                    int src = __shfl_sync(0xffffffffu, my, idx);
                    if (idx < m) {
                        uint2 qw = Q2[src * 16 + li];
                        __half2 qa = *reinterpret_cast<const __half2*>(&qw.x);
                        __half2 qb = *reinterpret_cast<const __half2*>(&qw.y);
                        __half2 ta = __hadd2(pa, qa);
                        __half2 tb = __hadd2(pb, qb);
                        __half2 va = __hfma2(ta, sc2a, sh2a);
                        __half2 vb = __hfma2(tb, sc2b, sh2b);
                        __half2 ya = __hmax2(va, __hmul2(va, slope));
                        __half2 yb = __hmax2(vb, __hmul2(vb, slope));
                        float2 fa = __half22float2(ya);
                        float2 fb = __half22float2(yb);
                        a0 += fa.x; a1 += fa.y; a2 += fb.x; a3 += fb.y;
                    }
                }
            }
        }
        a0 += __shfl_down_sync(0xffffffffu, a0, 16);
        a1 += __shfl_down_sync(0xffffffffu, a1, 16);
        a2 += __shfl_down_sync(0xffffffffu, a2, 16);
        a3 += __shfl_down_sync(0xffffffffu, a3, 16);
        if (h == 0) {
            float inv = (deg > 0) ? (1.0f / (float)deg) : 0.f;
            float4 r = make_float4(a0 * inv, a1 * inv, a2 * inv, a3 * inv);
            *reinterpret_cast<float4*>(&out[(size_t)n * 64 + 4 * li]) = r;
        }
    }
}

// ---------------------------------------------------------------------------
extern "C" void kernel_launch(void* const* d_in, const int* in_sizes, int n_in,
                              void* d_out, int out_size) {
    const float* feat  = (const float*)d_in[0];
    const int*   ei    = (const int*)d_in[1];
    const float* W     = (const float*)d_in[2];
    // d_in[3] = b: cancels out of BN, unused
    const float* gamma = (const float*)d_in[4];
    const float* beta  = (const float*)d_in[5];
    float* out = (float*)d_out;

    void* p_cnt;
    cudaGetSymbolAddress(&p_cnt, g_cnt);
    cudaMemsetAsync(p_cnt, 0, (size_t)NN * sizeof(int));

    gemm_pq_cnt<<<GEMM_BLOCKS + CNT_BLOCKS, 256>>>(feat, W, ei);
    scan_alloc<<<SCAN_BLOCKS, 1024>>>();
    csr_fill<<<(EE / 4 + 255) / 256, 256>>>(ei);
    edge_stats_csr<<<1184, 256>>>();
    agg_csr<<<1184, 256>>>(out, gamma, beta);
}